// round 12
// baseline (speedup 1.0000x reference)
#include <cuda_runtime.h>
#include <cstdint>
#include <math.h>

typedef unsigned long long ull;

#define EPS 1e-5f

// ---------------- scratch (device globals; no allocations allowed) ----------
__device__ float  g_om[8 * 27 * 64 * 64];          // offset-conv output
__device__ float  g_out1[8 * 256 * 64 * 64];       // DCN output (pre-BN)
__device__ float  g_raw[4 * 8 * 256 * 64 * 64];    // convT output per parity (pre-BN)
__device__ float  g_wdT[9 * 256 * 256];            // DCN weights [tap][c][o], tf32 bits
__device__ float  g_wctT[16 * 256 * 256];          // convT weights [par*4+tp][c][o], tf32 bits
__device__ float  g_woT[9 * 256 * 32];             // offset-conv weights [tap][c][o(pad32)]
__device__ double g_red[1024];                     // sums/sumsqs for the two BNs
__device__ float  g_s1[256], g_t1[256], g_s2[256], g_t2[256];

// ---------------- packed f32x2 helpers (k_off only) --------------------------
__device__ __forceinline__ ull pk2(float a, float b) {
    ull r; asm("mov.b64 %0, {%1,%2};" : "=l"(r) : "f"(a), "f"(b)); return r;
}
__device__ __forceinline__ void upk2(ull v, float& a, float& b) {
    asm("mov.b64 {%0,%1}, %2;" : "=f"(a), "=f"(b) : "l"(v));
}
__device__ __forceinline__ void ffma2(ull& d, ull a, ull b) {
    asm("fma.rn.f32x2 %0, %1, %2, %0;" : "+l"(d) : "l"(a), "l"(b));
}

// ---------------- tf32 helpers -----------------------------------------------
__device__ __forceinline__ uint32_t to_tf32(float f) {
    uint32_t u; asm("cvt.rna.tf32.f32 %0, %1;" : "=r"(u) : "f"(f)); return u;
}

#define MMA_TF32(dd, aa, b0, b1) \
    asm volatile("mma.sync.aligned.m16n8k8.row.col.f32.tf32.tf32.f32 " \
        "{%0,%1,%2,%3}, {%4,%5,%6,%7}, {%8,%9}, {%0,%1,%2,%3};" \
        : "+f"((dd)[0]), "+f"((dd)[1]), "+f"((dd)[2]), "+f"((dd)[3]) \
        : "r"((aa)[0]), "r"((aa)[1]), "r"((aa)[2]), "r"((aa)[3]), \
          "r"(b0), "r"(b1))

// SMEM float-index layout (B now read straight from L2; only A staged):
//   [0:256) aux0 (bias / s1)   [256:512) aux1 (t1)
//   A tile [32 k][72] = 2304 floats : A0 @512, A1 @2816
#define SMF_A(b)  (512 + (b) * 2304)
#define SM_SZ     (5120 * 4)

// ---------------- weight prep -----------------------------------------------
__global__ void prep_wd(const float* __restrict__ w) {  // w_dcn [o][c][3][3]
    int idx = blockIdx.x * blockDim.x + threadIdx.x;
    if (idx >= 9 * 65536) return;
    int tap = idx >> 16, c = (idx >> 8) & 255, o = idx & 255;
    g_wdT[idx] = __uint_as_float(to_tf32(w[((o << 8) + c) * 9 + tap]));
}

__global__ void prep_wct(const float* __restrict__ w) {  // w_ct [i][o][4][4]
    int idx = blockIdx.x * blockDim.x + threadIdx.x;
    if (idx >= 16 * 65536) return;
    int q = idx >> 16, c = (idx >> 8) & 255, o = idx & 255;
    int par = q >> 2, tp = q & 3;
    int py = par >> 1, px = par & 1, ty = tp >> 1, tx = tp & 1;
    int a = py ? (ty ? 0 : 2) : (ty ? 1 : 3);
    int b = px ? (tx ? 0 : 2) : (tx ? 1 : 3);
    g_wctT[idx] = __uint_as_float(to_tf32(w[(((c << 8) + o) << 4) + (a << 2) + b]));
}

__global__ void prep_wo(const float* __restrict__ w) {  // w_off [27][c][3][3]
    int idx = blockIdx.x * blockDim.x + threadIdx.x;
    if (idx >= 9 * 256 * 32) return;
    int tap = idx >> 13, c = (idx >> 5) & 255, o = idx & 31;
    g_woT[idx] = (o < 27) ? w[((o << 8) + c) * 9 + tap] : 0.f;
}

__global__ void k_zero() {
    int t = threadIdx.x;
    g_red[t] = 0.0; g_red[256 + t] = 0.0; g_red[512 + t] = 0.0; g_red[768 + t] = 0.0;
}

// ---------------- offset conv: 256->27(pad 32), 3x3 SAME (fp32, exact) ------
__global__ void __launch_bounds__(256, 2) k_off(const float* __restrict__ x,
                                                const float* __restrict__ boff) {
    extern __shared__ float vsm[];             // [256 c][64 p]
    const int t = threadIdx.x, y = blockIdx.x, n = blockIdx.y;
    const int o  = t & 31;
    const int p0 = (t >> 5) * 8;
    const int p  = t & 63;
    const int cg = t >> 6;

    ull acc[4];
    float bo = (o < 27) ? boff[o] : 0.f;
    ull bb = pk2(bo, bo);
    acc[0] = bb; acc[1] = bb; acc[2] = bb; acc[3] = bb;

    const float* xn = x + ((size_t)n << 20);

    for (int tap = 0; tap < 9; tap++) {
        const int ki = tap / 3, kj = tap - 3 * ki;
        const int yy = y + ki - 1;
        const int xx = p + kj - 1;
        const bool valid = (yy >= 0) && (yy < 64) && (xx >= 0) && (xx < 64);
        const float* src = xn + yy * 64 + xx;
        #pragma unroll 4
        for (int i = 0; i < 64; i++) {
            const int c = cg + (i << 2);
            vsm[(c << 6) + p] = valid ? src[(size_t)c << 12] : 0.f;
        }
        __syncthreads();
        const float* wb = g_woT + ((tap << 8) << 5);
        #pragma unroll 2
        for (int c = 0; c < 256; c++) {
            float w = wb[(c << 5) + o];
            ull wd = pk2(w, w);
            const ulonglong2* vp = (const ulonglong2*)(vsm + (c << 6) + p0);
            ulonglong2 va = vp[0], vb = vp[1];
            ffma2(acc[0], wd, va.x);
            ffma2(acc[1], wd, va.y);
            ffma2(acc[2], wd, vb.x);
            ffma2(acc[3], wd, vb.y);
        }
        __syncthreads();
    }

    if (o < 27) {
        float f0,f1,f2,f3,f4,f5,f6,f7;
        upk2(acc[0], f0, f1); upk2(acc[1], f2, f3);
        upk2(acc[2], f4, f5); upk2(acc[3], f6, f7);
        float* op = g_om + (((size_t)(n * 27 + o) * 64 + y) << 6) + p0;
        *(float4*)op       = make_float4(f0, f1, f2, f3);
        *(float4*)(op + 4) = make_float4(f4, f5, f6, f7);
    }
}

// ---------------- mma tile: A from smem, B fragments direct from L2 ----------
__device__ __forceinline__ void mma_tile_g(float d[4][4][4], const float* smf,
                                           int bufA, const uint32_t* __restrict__ Bg,
                                           int wid, int g, int tid) {
    const uint32_t* Au = (const uint32_t*)(smf + bufA);
    #pragma unroll
    for (int ks = 0; ks < 4; ks++) {
        const int k0 = (ks << 3) + tid;
        uint32_t a[4][4];
        #pragma unroll
        for (int mt = 0; mt < 4; mt++) {
            const int r0 = (mt << 4) + g;
            a[mt][0] = Au[k0 * 72 + r0];
            a[mt][1] = Au[k0 * 72 + r0 + 8];
            a[mt][2] = Au[(k0 + 4) * 72 + r0];
            a[mt][3] = Au[(k0 + 4) * 72 + r0 + 8];
        }
        #pragma unroll
        for (int nt = 0; nt < 4; nt++) {
            const int nb = (wid << 5) + (nt << 3) + g;
            uint32_t b0 = __ldg(Bg + (k0 << 8) + nb);
            uint32_t b1 = __ldg(Bg + ((k0 + 4) << 8) + nb);
            #pragma unroll
            for (int mt = 0; mt < 4; mt++)
                MMA_TF32(d[mt][nt], a[mt], b0, b1);
        }
    }
}

// ---------------- DCNv2 via tf32 mma.sync: M=64px, N=256o, K=9x256 ----------
__global__ void __launch_bounds__(256, 2) k_dcn_mma(const float* __restrict__ x,
                                                    const float* __restrict__ bdcn) {
    extern __shared__ __align__(16) float smf[];
    const int t = threadIdx.x, y = blockIdx.x, n = blockIdx.y;
    const int wid = t >> 5, lane = t & 31;
    const int g = lane >> 2, tid = lane & 3;
    const int p = t & 63, cq = t >> 6;

    smf[t] = bdcn[t];                           // bias in [0:256)

    float d[4][4][4];
    #pragma unroll
    for (int i = 0; i < 4; i++)
        #pragma unroll
        for (int j = 0; j < 4; j++)
            #pragma unroll
            for (int k = 0; k < 4; k++) d[i][j][k] = 0.f;

    const float* xn = x + ((size_t)n << 20);
    float wr0 = 0.f, wr1 = 0.f, wc0 = 0.f, wc1 = 0.f;
    int abase = 0;
    float va[8];

    #define DCN_PARAMS(tap_) do { \
        const int ki = (tap_) / 3, kj = (tap_) - 3 * ki; \
        const float offy = g_om[(((n * 27 + 2 * (tap_))     * 64 + y) << 6) + p]; \
        const float offx = g_om[(((n * 27 + 2 * (tap_) + 1) * 64 + y) << 6) + p]; \
        const float mm   = g_om[(((n * 27 + 18 + (tap_))    * 64 + y) << 6) + p]; \
        const float mask = 1.f / (1.f + __expf(-mm)); \
        const float ys = (float)(y + ki - 1) + offy; \
        const float xs = (float)(p + kj - 1) + offx; \
        const float fy0 = floorf(ys), fx0 = floorf(xs); \
        const float dy = ys - fy0, dx = xs - fx0; \
        const int iy0 = (int)fy0, ix0 = (int)fx0; \
        wr0 = (iy0 >= 0 && iy0 <= 62) ? (1.f - dy) : ((iy0 == -1) ? dy : 0.f); \
        wr1 = (iy0 >= 0 && iy0 <= 62) ? dy : ((iy0 == 63) ? (1.f - dy) : 0.f); \
        wc0 = (ix0 >= 0 && ix0 <= 62) ? (1.f - dx) : ((ix0 == -1) ? dx : 0.f); \
        wc1 = (ix0 >= 0 && ix0 <= 62) ? dx : ((ix0 == 63) ? (1.f - dx) : 0.f); \
        wr0 *= mask; wr1 *= mask; \
        const int rb = min(max(iy0, 0), 62), cb = min(max(ix0, 0), 62); \
        abase = rb * 64 + cb; \
    } while (0)

    #define DCN_GATHER(kc_) do { \
        _Pragma("unroll") \
        for (int j = 0; j < 8; j++) { \
            const int cl = (cq << 3) + j; \
            const float* xc = xn + ((size_t)(((kc_) << 5) + cl) << 12); \
            va[j] = wr0 * (wc0 * xc[abase]      + wc1 * xc[abase + 1]) \
                  + wr1 * (wc0 * xc[abase + 64] + wc1 * xc[abase + 65]); \
        } \
    } while (0)

    #define STS_A(bufA_) do { \
        float* dstA = smf + (bufA_); \
        _Pragma("unroll") \
        for (int j = 0; j < 8; j++) { \
            const int cl = (cq << 3) + j; \
            dstA[cl * 72 + p] = __uint_as_float(to_tf32(va[j])); \
        } \
    } while (0)

    // prologue: stage chunk 0 into buffer 0
    DCN_PARAMS(0);
    DCN_GATHER(0);
    STS_A(SMF_A(0));
    __syncthreads();

    for (int it = 0; it < 72; it++) {
        const int buf = it & 1;
        const int tap = it >> 3, kc = it & 7;
        if (it < 71) {
            const int s = it + 1;
            const int stap = s >> 3, skc = s & 7;
            if (skc == 0) DCN_PARAMS(stap);
            DCN_GATHER(skc);
        }
        const uint32_t* Bg = (const uint32_t*)g_wdT + (((size_t)(tap << 8) + (kc << 5)) << 8);
        mma_tile_g(d, smf, SMF_A(buf), Bg, wid, g, tid);
        if (it < 71) STS_A(SMF_A(buf ^ 1));
        __syncthreads();
    }

    // epilogue: +bias, store to g_out1[n][o][y][x]; fused BN1 stats
    float rs[4][2], rq[4][2];
    #pragma unroll
    for (int nt = 0; nt < 4; nt++) { rs[nt][0] = rs[nt][1] = rq[nt][0] = rq[nt][1] = 0.f; }

    float* ob = g_out1 + ((size_t)n << 20) + (y << 6);
    #pragma unroll
    for (int mt = 0; mt < 4; mt++) {
        const int x0 = (mt << 4) + g;
        #pragma unroll
        for (int nt = 0; nt < 4; nt++) {
            const int o0 = (wid << 5) + (nt << 3) + (tid << 1);
            const float b0v = smf[o0], b1v = smf[o0 + 1];
            float w0 = d[mt][nt][0] + b0v, w1 = d[mt][nt][1] + b1v;
            float w2 = d[mt][nt][2] + b0v, w3 = d[mt][nt][3] + b1v;
            ob[((size_t)o0 << 12) + x0]           = w0;
            ob[((size_t)(o0 + 1) << 12) + x0]     = w1;
            ob[((size_t)o0 << 12) + x0 + 8]       = w2;
            ob[((size_t)(o0 + 1) << 12) + x0 + 8] = w3;
            rs[nt][0] += w0 + w2;  rq[nt][0] += w0 * w0 + w2 * w2;
            rs[nt][1] += w1 + w3;  rq[nt][1] += w1 * w1 + w3 * w3;
        }
    }
    #pragma unroll
    for (int nt = 0; nt < 4; nt++)
        #pragma unroll
        for (int c2 = 0; c2 < 2; c2++) {
            float s = rs[nt][c2], q = rq[nt][c2];
            #pragma unroll
            for (int off = 4; off < 32; off <<= 1) {
                s += __shfl_down_sync(0xffffffffu, s, off);
                q += __shfl_down_sync(0xffffffffu, q, off);
            }
            if (lane < 4) {
                const int ch = (wid << 5) + (nt << 3) + (tid << 1) + c2;
                atomicAdd(&g_red[ch], (double)s);
                atomicAdd(&g_red[256 + ch], (double)q);
            }
        }
}

// ---------------- convT via tf32 mma.sync: per parity, K=4x256 --------------
__global__ void __launch_bounds__(256, 2) k_convt_mma() {
    extern __shared__ __align__(16) float smf[];
    const int t = threadIdx.x, y = blockIdx.x, n = blockIdx.y, par = blockIdx.z;
    const int py = par >> 1, pxs = par & 1;
    const int wid = t >> 5, lane = t & 31;
    const int g = lane >> 2, tid = lane & 3;
    const int p = t & 63, cq = t >> 6;

    smf[t] = g_s1[t];
    smf[256 + t] = g_t1[t];

    float d[4][4][4];
    #pragma unroll
    for (int i = 0; i < 4; i++)
        #pragma unroll
        for (int j = 0; j < 4; j++)
            #pragma unroll
            for (int k = 0; k < 4; k++) d[i][j][k] = 0.f;

    const float* srcn = g_out1 + ((size_t)n << 20);
    int soff = 0; bool valid = false;
    float va[8];

    #define CT_PARAMS(tp_) do { \
        const int t_y = (tp_) >> 1, t_x = (tp_) & 1; \
        const int yy = y + t_y - 1 + py; \
        const int xx = p + t_x - 1 + pxs; \
        valid = (yy >= 0) && (yy < 64) && (xx >= 0) && (xx < 64); \
        soff = valid ? (yy * 64 + xx) : 0; \
    } while (0)

    #define CT_GATHER(kc_) do { \
        _Pragma("unroll") \
        for (int j = 0; j < 8; j++) { \
            const int cl = (cq << 3) + j; \
            const int c = ((kc_) << 5) + cl; \
            float v = 0.f; \
            if (valid) { \
                float r = srcn[((size_t)c << 12) + soff]; \
                v = fmaxf(smf[c] * r + smf[256 + c], 0.f); \
            } \
            va[j] = v; \
        } \
    } while (0)

    #define CT_STS_A(bufA_) do { \
        float* dstA = smf + (bufA_); \
        _Pragma("unroll") \
        for (int j = 0; j < 8; j++) { \
            const int cl = (cq << 3) + j; \
            dstA[cl * 72 + p] = __uint_as_float(to_tf32(va[j])); \
        } \
    } while (0)

    // s1/t1 staged above must be visible before CT_GATHER reads them
    __syncthreads();

    CT_PARAMS(0);
    CT_GATHER(0);
    CT_STS_A(SMF_A(0));
    __syncthreads();

    for (int it = 0; it < 32; it++) {
        const int buf = it & 1;
        const int tp = it >> 3, kc = it & 7;
        if (it < 31) {
            const int s = it + 1;
            const int stp = s >> 3, skc = s & 7;
            if (skc == 0) CT_PARAMS(stp);
            CT_GATHER(skc);
        }
        const uint32_t* Bg = (const uint32_t*)g_wctT +
                             (((size_t)((par * 4 + tp) << 8) + (kc << 5)) << 8);
        mma_tile_g(d, smf, SMF_A(buf), Bg, wid, g, tid);
        if (it < 31) CT_STS_A(SMF_A(buf ^ 1));
        __syncthreads();
    }

    // epilogue: store raw; fused BN2 stats
    float rs[4][2], rq[4][2];
    #pragma unroll
    for (int nt = 0; nt < 4; nt++) { rs[nt][0] = rs[nt][1] = rq[nt][0] = rq[nt][1] = 0.f; }

    float* ob = g_raw + (((size_t)par * 8 + n) << 20) + (y << 6);
    #pragma unroll
    for (int mt = 0; mt < 4; mt++) {
        const int x0 = (mt << 4) + g;
        #pragma unroll
        for (int nt = 0; nt < 4; nt++) {
            const int o0 = (wid << 5) + (nt << 3) + (tid << 1);
            float w0 = d[mt][nt][0], w1 = d[mt][nt][1];
            float w2 = d[mt][nt][2], w3 = d[mt][nt][3];
            ob[((size_t)o0 << 12) + x0]           = w0;
            ob[((size_t)(o0 + 1) << 12) + x0]     = w1;
            ob[((size_t)o0 << 12) + x0 + 8]       = w2;
            ob[((size_t)(o0 + 1) << 12) + x0 + 8] = w3;
            rs[nt][0] += w0 + w2;  rq[nt][0] += w0 * w0 + w2 * w2;
            rs[nt][1] += w1 + w3;  rq[nt][1] += w1 * w1 + w3 * w3;
        }
    }
    #pragma unroll
    for (int nt = 0; nt < 4; nt++)
        #pragma unroll
        for (int c2 = 0; c2 < 2; c2++) {
            float s = rs[nt][c2], q = rq[nt][c2];
            #pragma unroll
            for (int off = 4; off < 32; off <<= 1) {
                s += __shfl_down_sync(0xffffffffu, s, off);
                q += __shfl_down_sync(0xffffffffu, q, off);
            }
            if (lane < 4) {
                const int ch = (wid << 5) + (nt << 3) + (tid << 1) + c2;
                atomicAdd(&g_red[512 + ch], (double)s);
                atomicAdd(&g_red[768 + ch], (double)q);
            }
        }
}

// ---------------- BN stats --------------------------------------------------
__global__ void k_stats1(const float* __restrict__ g, const float* __restrict__ b) {
    int t = threadIdx.x;
    double sum = g_red[t], sq = g_red[256 + t];
    double m = sum / 32768.0;
    float var = (float)(sq / 32768.0 - m * m);
    var = fmaxf(var, 0.f);
    float s = g[t] * rsqrtf(var + EPS);
    g_s1[t] = s;
    g_t1[t] = b[t] - (float)m * s;
}

__global__ void k_stats2(const float* __restrict__ g, const float* __restrict__ b) {
    int t = threadIdx.x;
    double sum = g_red[512 + t], sq = g_red[768 + t];
    double m = sum / 131072.0;
    float var = (float)(sq / 131072.0 - m * m);
    var = fmaxf(var, 0.f);
    float s = g[t] * rsqrtf(var + EPS);
    g_s2[t] = s;
    g_t2[t] = b[t] - (float)m * s;
}

// ---------------- finalize: BN2 + ReLU, de-interleave parities --------------
__global__ void k_final(float* __restrict__ out) {
    int idx = blockIdx.x * 256 + threadIdx.x;
    int tx = idx & 63;
    int oy = (idx >> 6) & 127;
    int o  = (idx >> 13) & 255;
    int n  = idx >> 21;
    int py = oy & 1, ty = oy >> 1;
    size_t b0 = ((((size_t)(2 * py + 0) * 8 + n) * 256 + o) << 12) + (ty << 6) + tx;
    size_t b1 = ((((size_t)(2 * py + 1) * 8 + n) * 256 + o) << 12) + (ty << 6) + tx;
    float r0 = g_raw[b0], r1 = g_raw[b1];
    float s = g_s2[o], tt = g_t2[o];
    float2 w2;
    w2.x = fmaxf(s * r0 + tt, 0.f);
    w2.y = fmaxf(s * r1 + tt, 0.f);
    *(float2*)(out + ((((size_t)n * 256 + o) * 128 + oy) << 7) + 2 * tx) = w2;
}

// ---------------- launch ----------------------------------------------------
extern "C" void kernel_launch(void* const* d_in, const int* in_sizes, int n_in,
                              void* d_out, int out_size) {
    const float* x      = (const float*)d_in[0];
    const float* w_off  = (const float*)d_in[1];
    const float* b_off  = (const float*)d_in[2];
    const float* w_dcn  = (const float*)d_in[3];
    const float* b_dcn  = (const float*)d_in[4];
    const float* gamma1 = (const float*)d_in[5];
    const float* beta1  = (const float*)d_in[6];
    const float* w_ct   = (const float*)d_in[7];
    const float* gamma2 = (const float*)d_in[8];
    const float* beta2  = (const float*)d_in[9];
    float* out = (float*)d_out;

    cudaFuncSetAttribute(k_off,       cudaFuncAttributeMaxDynamicSharedMemorySize, 65536);
    cudaFuncSetAttribute(k_dcn_mma,   cudaFuncAttributeMaxDynamicSharedMemorySize, SM_SZ);
    cudaFuncSetAttribute(k_convt_mma, cudaFuncAttributeMaxDynamicSharedMemorySize, SM_SZ);

    prep_wd<<<(9 * 65536 + 255) / 256, 256>>>(w_dcn);
    prep_wct<<<(16 * 65536 + 255) / 256, 256>>>(w_ct);
    prep_wo<<<(9 * 256 * 32 + 255) / 256, 256>>>(w_off);
    k_zero<<<1, 256>>>();

    k_off<<<dim3(64, 8), 256, 65536>>>(x, b_off);
    k_dcn_mma<<<dim3(64, 8), 256, SM_SZ>>>(x, b_dcn);

    k_stats1<<<1, 256>>>(gamma1, beta1);

    k_convt_mma<<<dim3(64, 8, 4), 256, SM_SZ>>>();

    k_stats2<<<1, 256>>>(gamma2, beta2);

    k_final<<<65536, 256>>>(out);
}

// round 16
// speedup vs baseline: 1.0870x; 1.0870x over previous
#include <cuda_runtime.h>
#include <cstdint>
#include <math.h>

typedef unsigned long long ull;

#define EPS 1e-5f

// ---------------- scratch (device globals; no allocations allowed) ----------
__device__ float  g_om[8 * 27 * 64 * 64];          // offset-conv output
__device__ float  g_out1[8 * 256 * 64 * 64];       // DCN output (pre-BN)
__device__ float  g_raw[4 * 8 * 256 * 64 * 64];    // convT output per parity (pre-BN)
__device__ float  g_wdT[9 * 256 * 256];            // DCN weights [tap][c][o], tf32 bits
__device__ float  g_wctT[16 * 256 * 256];          // convT weights [par*4+tp][c][o], tf32 bits
__device__ float  g_woT[9 * 256 * 32];             // offset-conv weights [tap][c][o(pad32)]
__device__ double g_red[1024];                     // sums/sumsqs for the two BNs
__device__ float  g_s1[256], g_t1[256], g_s2[256], g_t2[256];

// ---------------- packed f32x2 helpers (k_off only) --------------------------
__device__ __forceinline__ ull pk2(float a, float b) {
    ull r; asm("mov.b64 %0, {%1,%2};" : "=l"(r) : "f"(a), "f"(b)); return r;
}
__device__ __forceinline__ void upk2(ull v, float& a, float& b) {
    asm("mov.b64 {%0,%1}, %2;" : "=f"(a), "=f"(b) : "l"(v));
}
__device__ __forceinline__ void ffma2(ull& d, ull a, ull b) {
    asm("fma.rn.f32x2 %0, %1, %2, %0;" : "+l"(d) : "l"(a), "l"(b));
}

// ---------------- tf32 / async helpers ---------------------------------------
__device__ __forceinline__ uint32_t to_tf32(float f) {
    uint32_t u; asm("cvt.rna.tf32.f32 %0, %1;" : "=r"(u) : "f"(f)); return u;
}
__device__ __forceinline__ uint32_t smem_u32(const void* p) {
    uint32_t a;
    asm("{ .reg .u64 t; cvta.to.shared.u64 t, %1; cvt.u32.u64 %0, t; }" : "=r"(a) : "l"(p));
    return a;
}
__device__ __forceinline__ void cp_async16(uint32_t dst, const void* src) {
    asm volatile("cp.async.ca.shared.global [%0], [%1], 16;" :: "r"(dst), "l"(src));
}
#define CP_COMMIT() asm volatile("cp.async.commit_group;" ::: "memory")
#define CP_WAIT0()  asm volatile("cp.async.wait_group 0;" ::: "memory")

#define MMA_TF32(dd, aa, b0, b1) \
    asm volatile("mma.sync.aligned.m16n8k8.row.col.f32.tf32.tf32.f32 " \
        "{%0,%1,%2,%3}, {%4,%5,%6,%7}, {%8,%9}, {%0,%1,%2,%3};" \
        : "+f"((dd)[0]), "+f"((dd)[1]), "+f"((dd)[2]), "+f"((dd)[3]) \
        : "r"((aa)[0]), "r"((aa)[1]), "r"((aa)[2]), "r"((aa)[3]), \
          "r"(b0), "r"(b1))

// ---- k_dcn SMEM float-index layout (round-11, proven):
//   [0:256) aux0 (bias)   [256:512) unused
//   A tile [32 k][72]  = 2304 floats : A0 @512,  A1 @2816
//   B tile [32 k][264] = 8448 floats : B0 @5120, B1 @13568
#define SMF_A(b)  (512 + (b) * 2304)
#define SMF_B(b)  (5120 + (b) * 8448)
#define SM_SZ     (22016 * 4)

// ---- k_convt SMEM float-index layout (512 threads, M=128 = 2 rows):
//   [0:256) s1   [256:512) t1
//   A buf b @ 512 + b*4608 (row r at +r*2304, each [32 k][72])
//   B buf b @ 9728 + b*8448 ([32 k][264])
#define CT_SMF_A(b) (512 + (b) * 4608)
#define CT_SMF_B(b) (9728 + (b) * 8448)
#define CT_SM_SZ    (26624 * 4)

// ---------------- weight prep -----------------------------------------------
__global__ void prep_wd(const float* __restrict__ w) {  // w_dcn [o][c][3][3]
    int idx = blockIdx.x * blockDim.x + threadIdx.x;
    if (idx >= 9 * 65536) return;
    int tap = idx >> 16, c = (idx >> 8) & 255, o = idx & 255;
    g_wdT[idx] = __uint_as_float(to_tf32(w[((o << 8) + c) * 9 + tap]));
}

__global__ void prep_wct(const float* __restrict__ w) {  // w_ct [i][o][4][4]
    int idx = blockIdx.x * blockDim.x + threadIdx.x;
    if (idx >= 16 * 65536) return;
    int q = idx >> 16, c = (idx >> 8) & 255, o = idx & 255;
    int par = q >> 2, tp = q & 3;
    int py = par >> 1, px = par & 1, ty = tp >> 1, tx = tp & 1;
    int a = py ? (ty ? 0 : 2) : (ty ? 1 : 3);
    int b = px ? (tx ? 0 : 2) : (tx ? 1 : 3);
    g_wctT[idx] = __uint_as_float(to_tf32(w[(((c << 8) + o) << 4) + (a << 2) + b]));
}

__global__ void prep_wo(const float* __restrict__ w) {  // w_off [27][c][3][3]; also zeroes g_red
    int idx = blockIdx.x * blockDim.x + threadIdx.x;
    if (idx < 1024) g_red[idx] = 0.0;
    if (idx >= 9 * 256 * 32) return;
    int tap = idx >> 13, c = (idx >> 5) & 255, o = idx & 31;
    g_woT[idx] = (o < 27) ? w[((o << 8) + c) * 9 + tap] : 0.f;
}

// ---------------- offset conv: 256->27(pad 32), 3x3 SAME (fp32, exact) ------
__global__ void __launch_bounds__(256, 2) k_off(const float* __restrict__ x,
                                                const float* __restrict__ boff) {
    extern __shared__ float vsm[];             // [256 c][64 p]
    const int t = threadIdx.x, y = blockIdx.x, n = blockIdx.y;
    const int o  = t & 31;
    const int p0 = (t >> 5) * 8;
    const int p  = t & 63;
    const int cg = t >> 6;

    ull acc[4];
    float bo = (o < 27) ? boff[o] : 0.f;
    ull bb = pk2(bo, bo);
    acc[0] = bb; acc[1] = bb; acc[2] = bb; acc[3] = bb;

    const float* xn = x + ((size_t)n << 20);

    for (int tap = 0; tap < 9; tap++) {
        const int ki = tap / 3, kj = tap - 3 * ki;
        const int yy = y + ki - 1;
        const int xx = p + kj - 1;
        const bool valid = (yy >= 0) && (yy < 64) && (xx >= 0) && (xx < 64);
        const float* src = xn + yy * 64 + xx;
        #pragma unroll 4
        for (int i = 0; i < 64; i++) {
            const int c = cg + (i << 2);
            vsm[(c << 6) + p] = valid ? src[(size_t)c << 12] : 0.f;
        }
        __syncthreads();
        const float* wb = g_woT + ((tap << 8) << 5);
        #pragma unroll 2
        for (int c = 0; c < 256; c++) {
            float w = wb[(c << 5) + o];
            ull wd = pk2(w, w);
            const ulonglong2* vp = (const ulonglong2*)(vsm + (c << 6) + p0);
            ulonglong2 va = vp[0], vb = vp[1];
            ffma2(acc[0], wd, va.x);
            ffma2(acc[1], wd, va.y);
            ffma2(acc[2], wd, vb.x);
            ffma2(acc[3], wd, vb.y);
        }
        __syncthreads();
    }

    if (o < 27) {
        float f0,f1,f2,f3,f4,f5,f6,f7;
        upk2(acc[0], f0, f1); upk2(acc[1], f2, f3);
        upk2(acc[2], f4, f5); upk2(acc[3], f6, f7);
        float* op = g_om + (((size_t)(n * 27 + o) * 64 + y) << 6) + p0;
        *(float4*)op       = make_float4(f0, f1, f2, f3);
        *(float4*)(op + 4) = make_float4(f4, f5, f6, f7);
    }
}

// ---------------- shared mma tile compute (round-7 proven form) --------------
__device__ __forceinline__ void mma_tile(float d[4][4][4], const float* Af,
                                         const float* Bf, int ng, int g, int tid) {
    const uint32_t* Au = (const uint32_t*)Af;
    const uint32_t* Bu = (const uint32_t*)Bf;
    #pragma unroll
    for (int ks = 0; ks < 4; ks++) {
        const int k0 = (ks << 3) + tid;
        uint32_t a[4][4];
        #pragma unroll
        for (int mt = 0; mt < 4; mt++) {
            const int r0 = (mt << 4) + g;
            a[mt][0] = Au[k0 * 72 + r0];
            a[mt][1] = Au[k0 * 72 + r0 + 8];
            a[mt][2] = Au[(k0 + 4) * 72 + r0];
            a[mt][3] = Au[(k0 + 4) * 72 + r0 + 8];
        }
        #pragma unroll
        for (int nt = 0; nt < 4; nt++) {
            const int nb = (ng << 5) + (nt << 3) + g;
            uint32_t b0 = Bu[k0 * 264 + nb];
            uint32_t b1 = Bu[(k0 + 4) * 264 + nb];
            #pragma unroll
            for (int mt = 0; mt < 4; mt++)
                MMA_TF32(d[mt][nt], a[mt], b0, b1);
        }
    }
}

// B stage via cp.async (256-thread version): 8x16B per thread = 2048 float4.
__device__ __forceinline__ void stage_B_async(uint32_t sbase, int bufB,
                                              const float* img, int t) {
    #pragma unroll
    for (int i = 0; i < 8; i++) {
        int idx = t + (i << 8);
        int cl = idx >> 6, o4 = (idx & 63) << 2;
        cp_async16(sbase + (uint32_t)(bufB + cl * 264 + o4) * 4, img + (idx << 2));
    }
    CP_COMMIT();
}

// B stage via cp.async (512-thread version): 4x16B per thread = 2048 float4 exact.
__device__ __forceinline__ void stage_B_async512(uint32_t sbase, int bufB,
                                                 const float* img, int t) {
    #pragma unroll
    for (int i = 0; i < 4; i++) {
        int idx = t + (i << 9);
        int cl = idx >> 6, o4 = (idx & 63) << 2;
        cp_async16(sbase + (uint32_t)(bufB + cl * 264 + o4) * 4, img + (idx << 2));
    }
    CP_COMMIT();
}

// ---------------- DCNv2 via tf32 mma.sync (round-11 verbatim) ----------------
__global__ void __launch_bounds__(256, 2) k_dcn_mma(const float* __restrict__ x,
                                                    const float* __restrict__ bdcn) {
    extern __shared__ __align__(16) float smf[];
    const uint32_t sbase = smem_u32(smf);
    const int t = threadIdx.x, y = blockIdx.x, n = blockIdx.y;
    const int wid = t >> 5, lane = t & 31;
    const int g = lane >> 2, tid = lane & 3;
    const int p = t & 63, cq = t >> 6;

    smf[t] = bdcn[t];                           // bias in [0:256)

    float d[4][4][4];
    #pragma unroll
    for (int i = 0; i < 4; i++)
        #pragma unroll
        for (int j = 0; j < 4; j++)
            #pragma unroll
            for (int k = 0; k < 4; k++) d[i][j][k] = 0.f;

    const float* xn = x + ((size_t)n << 20);
    float wr0 = 0.f, wr1 = 0.f, wc0 = 0.f, wc1 = 0.f;
    int abase = 0;
    float va[8];

    #define DCN_PARAMS(tap_) do { \
        const int ki = (tap_) / 3, kj = (tap_) - 3 * ki; \
        const float offy = g_om[(((n * 27 + 2 * (tap_))     * 64 + y) << 6) + p]; \
        const float offx = g_om[(((n * 27 + 2 * (tap_) + 1) * 64 + y) << 6) + p]; \
        const float mm   = g_om[(((n * 27 + 18 + (tap_))    * 64 + y) << 6) + p]; \
        const float mask = 1.f / (1.f + __expf(-mm)); \
        const float ys = (float)(y + ki - 1) + offy; \
        const float xs = (float)(p + kj - 1) + offx; \
        const float fy0 = floorf(ys), fx0 = floorf(xs); \
        const float dy = ys - fy0, dx = xs - fx0; \
        const int iy0 = (int)fy0, ix0 = (int)fx0; \
        wr0 = (iy0 >= 0 && iy0 <= 62) ? (1.f - dy) : ((iy0 == -1) ? dy : 0.f); \
        wr1 = (iy0 >= 0 && iy0 <= 62) ? dy : ((iy0 == 63) ? (1.f - dy) : 0.f); \
        wc0 = (ix0 >= 0 && ix0 <= 62) ? (1.f - dx) : ((ix0 == -1) ? dx : 0.f); \
        wc1 = (ix0 >= 0 && ix0 <= 62) ? dx : ((ix0 == 63) ? (1.f - dx) : 0.f); \
        wr0 *= mask; wr1 *= mask; \
        const int rb = min(max(iy0, 0), 62), cb = min(max(ix0, 0), 62); \
        abase = rb * 64 + cb; \
    } while (0)

    #define DCN_GATHER(kc_) do { \
        _Pragma("unroll") \
        for (int j = 0; j < 8; j++) { \
            const int cl = (cq << 3) + j; \
            const float* xc = xn + ((size_t)(((kc_) << 5) + cl) << 12); \
            va[j] = wr0 * (wc0 * xc[abase]      + wc1 * xc[abase + 1]) \
                  + wr1 * (wc0 * xc[abase + 64] + wc1 * xc[abase + 65]); \
        } \
    } while (0)

    #define STS_A(bufA_) do { \
        float* dstA = smf + (bufA_); \
        _Pragma("unroll") \
        for (int j = 0; j < 8; j++) { \
            const int cl = (cq << 3) + j; \
            dstA[cl * 72 + p] = __uint_as_float(to_tf32(va[j])); \
        } \
    } while (0)

    // prologue: stage chunk 0 into buffer 0
    DCN_PARAMS(0);
    stage_B_async(sbase, SMF_B(0), g_wdT, t);
    DCN_GATHER(0);
    STS_A(SMF_A(0));
    CP_WAIT0();
    __syncthreads();

    for (int it = 0; it < 72; it++) {
        const int buf = it & 1;
        if (it < 71) {
            const int s = it + 1;
            const int stap = s >> 3, skc = s & 7;
            if (skc == 0) DCN_PARAMS(stap);
            stage_B_async(sbase, SMF_B(buf ^ 1),
                          g_wdT + (((size_t)(stap << 8) + (skc << 5)) << 8), t);
            DCN_GATHER(skc);
        }
        mma_tile(d, smf + SMF_A(buf), smf + SMF_B(buf), wid, g, tid);
        if (it < 71) STS_A(SMF_A(buf ^ 1));
        CP_WAIT0();
        __syncthreads();
    }

    // epilogue: +bias, store to g_out1[n][o][y][x]; fused BN1 stats
    float rs[4][2], rq[4][2];
    #pragma unroll
    for (int nt = 0; nt < 4; nt++) { rs[nt][0] = rs[nt][1] = rq[nt][0] = rq[nt][1] = 0.f; }

    float* ob = g_out1 + ((size_t)n << 20) + (y << 6);
    #pragma unroll
    for (int mt = 0; mt < 4; mt++) {
        const int x0 = (mt << 4) + g;
        #pragma unroll
        for (int nt = 0; nt < 4; nt++) {
            const int o0 = (wid << 5) + (nt << 3) + (tid << 1);
            const float b0v = smf[o0], b1v = smf[o0 + 1];
            float w0 = d[mt][nt][0] + b0v, w1 = d[mt][nt][1] + b1v;
            float w2 = d[mt][nt][2] + b0v, w3 = d[mt][nt][3] + b1v;
            ob[((size_t)o0 << 12) + x0]           = w0;
            ob[((size_t)(o0 + 1) << 12) + x0]     = w1;
            ob[((size_t)o0 << 12) + x0 + 8]       = w2;
            ob[((size_t)(o0 + 1) << 12) + x0 + 8] = w3;
            rs[nt][0] += w0 + w2;  rq[nt][0] += w0 * w0 + w2 * w2;
            rs[nt][1] += w1 + w3;  rq[nt][1] += w1 * w1 + w3 * w3;
        }
    }
    #pragma unroll
    for (int nt = 0; nt < 4; nt++)
        #pragma unroll
        for (int c2 = 0; c2 < 2; c2++) {
            float s = rs[nt][c2], q = rq[nt][c2];
            #pragma unroll
            for (int off = 4; off < 32; off <<= 1) {
                s += __shfl_down_sync(0xffffffffu, s, off);
                q += __shfl_down_sync(0xffffffffu, q, off);
            }
            if (lane < 4) {
                const int ch = (wid << 5) + (nt << 3) + (tid << 1) + c2;
                atomicAdd(&g_red[ch], (double)s);
                atomicAdd(&g_red[256 + ch], (double)q);
            }
        }
}

// ---------------- convT via tf32 mma.sync: 512 thr, M=128 (2 rows) ----------
__global__ void __launch_bounds__(512, 1) k_convt_mma() {
    extern __shared__ __align__(16) float smf[];
    const uint32_t sbase = smem_u32(smf);
    const int t = threadIdx.x, by = blockIdx.x, n = blockIdx.y, par = blockIdx.z;
    const int py = par >> 1, pxs = par & 1;
    const int wid = t >> 5, lane = t & 31;
    const int g = lane >> 2, tid = lane & 3;
    const int ng = wid & 7, mg = wid >> 3;
    const int y0 = by << 1;
    // gather decomposition: 512 thr x 8 vals = 32c x 128px
    const int p2 = t & 127;                 // pixel in 2-row tile
    const int grow = p2 >> 6, gx = p2 & 63; // gather row, x
    const int cq2 = t >> 7;                 // 0..3 channel quarter

    if (t < 256) { smf[t] = g_s1[t]; smf[256 + t] = g_t1[t]; }

    float d[4][4][4];
    #pragma unroll
    for (int i = 0; i < 4; i++)
        #pragma unroll
        for (int j = 0; j < 4; j++)
            #pragma unroll
            for (int k = 0; k < 4; k++) d[i][j][k] = 0.f;

    const float* srcn = g_out1 + ((size_t)n << 20);
    int soff = 0; bool valid = false;
    float va[8];

    #define CT_PARAMS(tp_) do { \
        const int t_y = (tp_) >> 1, t_x = (tp_) & 1; \
        const int yy = y0 + grow + t_y - 1 + py; \
        const int xx = gx + t_x - 1 + pxs; \
        valid = (yy >= 0) && (yy < 64) && (xx >= 0) && (xx < 64); \
        soff = valid ? (yy * 64 + xx) : 0; \
    } while (0)

    #define CT_GATHER(kc_) do { \
        _Pragma("unroll") \
        for (int j = 0; j < 8; j++) { \
            const int cl = (cq2 << 3) + j; \
            const int c = ((kc_) << 5) + cl; \
            float v = 0.f; \
            if (valid) { \
                float r = srcn[((size_t)c << 12) + soff]; \
                v = fmaxf(smf[c] * r + smf[256 + c], 0.f); \
            } \
            va[j] = v; \
        } \
    } while (0)

    #define CT_STS_A(bufA_) do { \
        float* dstA = smf + (bufA_) + grow * 2304; \
        _Pragma("unroll") \
        for (int j = 0; j < 8; j++) { \
            const int cl = (cq2 << 3) + j; \
            dstA[cl * 72 + gx] = __uint_as_float(to_tf32(va[j])); \
        } \
    } while (0)

    // s1/t1 must be visible before CT_GATHER reads them
    __syncthreads();

    CT_PARAMS(0);
    stage_B_async512(sbase, CT_SMF_B(0), g_wctT + (((size_t)(par * 4) << 8) << 8), t);
    CT_GATHER(0);
    CT_STS_A(CT_SMF_A(0));
    CP_WAIT0();
    __syncthreads();

    for (int it = 0; it < 32; it++) {
        const int buf = it & 1;
        if (it < 31) {
            const int s = it + 1;
            const int stp = s >> 3, skc = s & 7;
            if (skc == 0) CT_PARAMS(stp);
            stage_B_async512(sbase, CT_SMF_B(buf ^ 1),
                             g_wctT + (((size_t)((par * 4 + stp) << 8) + (skc << 5)) << 8), t);
            CT_GATHER(skc);
        }
        mma_tile(d, smf + CT_SMF_A(buf) + mg * 2304, smf + CT_SMF_B(buf), ng, g, tid);
        if (it < 31) CT_STS_A(CT_SMF_A(buf ^ 1));
        CP_WAIT0();
        __syncthreads();
    }

    // epilogue: store raw; fused BN2 stats
    float rs[4][2], rq[4][2];
    #pragma unroll
    for (int nt = 0; nt < 4; nt++) { rs[nt][0] = rs[nt][1] = rq[nt][0] = rq[nt][1] = 0.f; }

    float* ob = g_raw + (((size_t)par * 8 + n) << 20) + ((y0 + mg) << 6);
    #pragma unroll
    for (int mt = 0; mt < 4; mt++) {
        const int x0 = (mt << 4) + g;
        #pragma unroll
        for (int nt = 0; nt < 4; nt++) {
            const int o0 = (ng << 5) + (nt << 3) + (tid << 1);
            float w0 = d[mt][nt][0], w1 = d[mt][nt][1];
            float w2 = d[mt][nt][2], w3 = d[mt][nt][3];
            ob[((size_t)o0 << 12) + x0]           = w0;
            ob[((size_t)(o0 + 1) << 12) + x0]     = w1;
            ob[((size_t)o0 << 12) + x0 + 8]       = w2;
            ob[((size_t)(o0 + 1) << 12) + x0 + 8] = w3;
            rs[nt][0] += w0 + w2;  rq[nt][0] += w0 * w0 + w2 * w2;
            rs[nt][1] += w1 + w3;  rq[nt][1] += w1 * w1 + w3 * w3;
        }
    }
    #pragma unroll
    for (int nt = 0; nt < 4; nt++)
        #pragma unroll
        for (int c2 = 0; c2 < 2; c2++) {
            float s = rs[nt][c2], q = rq[nt][c2];
            #pragma unroll
            for (int off = 4; off < 32; off <<= 1) {
                s += __shfl_down_sync(0xffffffffu, s, off);
                q += __shfl_down_sync(0xffffffffu, q, off);
            }
            if (lane < 4) {
                const int ch = (ng << 5) + (nt << 3) + (tid << 1) + c2;
                atomicAdd(&g_red[512 + ch], (double)s);
                atomicAdd(&g_red[768 + ch], (double)q);
            }
        }
}

// ---------------- BN stats --------------------------------------------------
__global__ void k_stats1(const float* __restrict__ g, const float* __restrict__ b) {
    int t = threadIdx.x;
    double sum = g_red[t], sq = g_red[256 + t];
    double m = sum / 32768.0;
    float var = (float)(sq / 32768.0 - m * m);
    var = fmaxf(var, 0.f);
    float s = g[t] * rsqrtf(var + EPS);
    g_s1[t] = s;
    g_t1[t] = b[t] - (float)m * s;
}

__global__ void k_stats2(const float* __restrict__ g, const float* __restrict__ b) {
    int t = threadIdx.x;
    double sum = g_red[512 + t], sq = g_red[768 + t];
    double m = sum / 131072.0;
    float var = (float)(sq / 131072.0 - m * m);
    var = fmaxf(var, 0.f);
    float s = g[t] * rsqrtf(var + EPS);
    g_s2[t] = s;
    g_t2[t] = b[t] - (float)m * s;
}

// ---------------- finalize: BN2 + ReLU, de-interleave parities --------------
__global__ void k_final(float* __restrict__ out) {
    int idx = blockIdx.x * 256 + threadIdx.x;
    int tx = idx & 63;
    int oy = (idx >> 6) & 127;
    int o  = (idx >> 13) & 255;
    int n  = idx >> 21;
    int py = oy & 1, ty = oy >> 1;
    size_t b0 = ((((size_t)(2 * py + 0) * 8 + n) * 256 + o) << 12) + (ty << 6) + tx;
    size_t b1 = ((((size_t)(2 * py + 1) * 8 + n) * 256 + o) << 12) + (ty << 6) + tx;
    float r0 = g_raw[b0], r1 = g_raw[b1];
    float s = g_s2[o], tt = g_t2[o];
    float2 w2;
    w2.x = fmaxf(s * r0 + tt, 0.f);
    w2.y = fmaxf(s * r1 + tt, 0.f);
    *(float2*)(out + ((((size_t)n * 256 + o) * 128 + oy) << 7) + 2 * tx) = w2;
}

// ---------------- launch ----------------------------------------------------
extern "C" void kernel_launch(void* const* d_in, const int* in_sizes, int n_in,
                              void* d_out, int out_size) {
    const float* x      = (const float*)d_in[0];
    const float* w_off  = (const float*)d_in[1];
    const float* b_off  = (const float*)d_in[2];
    const float* w_dcn  = (const float*)d_in[3];
    const float* b_dcn  = (const float*)d_in[4];
    const float* gamma1 = (const float*)d_in[5];
    const float* beta1  = (const float*)d_in[6];
    const float* w_ct   = (const float*)d_in[7];
    const float* gamma2 = (const float*)d_in[8];
    const float* beta2  = (const float*)d_in[9];
    float* out = (float*)d_out;

    cudaFuncSetAttribute(k_off,       cudaFuncAttributeMaxDynamicSharedMemorySize, 65536);
    cudaFuncSetAttribute(k_dcn_mma,   cudaFuncAttributeMaxDynamicSharedMemorySize, SM_SZ);
    cudaFuncSetAttribute(k_convt_mma, cudaFuncAttributeMaxDynamicSharedMemorySize, CT_SM_SZ);

    prep_wd<<<(9 * 65536 + 255) / 256, 256>>>(w_dcn);
    prep_wct<<<(16 * 65536 + 255) / 256, 256>>>(w_ct);
    prep_wo<<<(9 * 256 * 32 + 255) / 256, 256>>>(w_off);

    k_off<<<dim3(64, 8), 256, 65536>>>(x, b_off);
    k_dcn_mma<<<dim3(64, 8), 256, SM_SZ>>>(x, b_dcn);

    k_stats1<<<1, 256>>>(gamma1, beta1);

    k_convt_mma<<<dim3(32, 8, 4), 512, CT_SM_SZ>>>();

    k_stats2<<<1, 256>>>(gamma2, beta2);

    k_final<<<65536, 256>>>(out);
}

// round 17
// speedup vs baseline: 1.0899x; 1.0027x over previous
#include <cuda_runtime.h>
#include <cstdint>
#include <math.h>

typedef unsigned long long ull;

#define EPS 1e-5f

// ---------------- scratch (device globals; no allocations allowed) ----------
__device__ float  g_om[8 * 27 * 64 * 64];          // offset-conv output
__device__ float  g_out1[8 * 256 * 64 * 64];       // DCN output (pre-BN)
__device__ float  g_raw[4 * 8 * 256 * 64 * 64];    // convT output per parity (pre-BN)
__device__ float  g_wdT[9 * 256 * 256];            // DCN weights [tap][c][o], tf32 bits
__device__ float  g_wctT[16 * 256 * 256];          // convT weights [par*4+tp][c][o], tf32 bits
__device__ float  g_woT[9 * 256 * 32];             // offset-conv weights [tap][c][o(pad32)]
__device__ double g_red[1024];                     // sums/sumsqs for the two BNs
__device__ float  g_s1[256], g_t1[256], g_s2[256], g_t2[256];

// ---------------- packed f32x2 helpers (k_off only) --------------------------
__device__ __forceinline__ ull pk2(float a, float b) {
    ull r; asm("mov.b64 %0, {%1,%2};" : "=l"(r) : "f"(a), "f"(b)); return r;
}
__device__ __forceinline__ void upk2(ull v, float& a, float& b) {
    asm("mov.b64 {%0,%1}, %2;" : "=f"(a), "=f"(b) : "l"(v));
}
__device__ __forceinline__ void ffma2(ull& d, ull a, ull b) {
    asm("fma.rn.f32x2 %0, %1, %2, %0;" : "+l"(d) : "l"(a), "l"(b));
}

// ---------------- tf32 / async helpers ---------------------------------------
__device__ __forceinline__ uint32_t to_tf32(float f) {
    uint32_t u; asm("cvt.rna.tf32.f32 %0, %1;" : "=r"(u) : "f"(f)); return u;
}
__device__ __forceinline__ uint32_t smem_u32(const void* p) {
    uint32_t a;
    asm("{ .reg .u64 t; cvta.to.shared.u64 t, %1; cvt.u32.u64 %0, t; }" : "=r"(a) : "l"(p));
    return a;
}
__device__ __forceinline__ void cp_async16(uint32_t dst, const void* src) {
    asm volatile("cp.async.ca.shared.global [%0], [%1], 16;" :: "r"(dst), "l"(src));
}
#define CP_COMMIT() asm volatile("cp.async.commit_group;" ::: "memory")
#define CP_WAIT0()  asm volatile("cp.async.wait_group 0;" ::: "memory")

#define MMA_TF32(dd, aa, b0, b1) \
    asm volatile("mma.sync.aligned.m16n8k8.row.col.f32.tf32.tf32.f32 " \
        "{%0,%1,%2,%3}, {%4,%5,%6,%7}, {%8,%9}, {%0,%1,%2,%3};" \
        : "+f"((dd)[0]), "+f"((dd)[1]), "+f"((dd)[2]), "+f"((dd)[3]) \
        : "r"((aa)[0]), "r"((aa)[1]), "r"((aa)[2]), "r"((aa)[3]), \
          "r"(b0), "r"(b1))

// ---- k_dcn SMEM float-index layout (round-11, proven):
//   [0:256) aux0 (bias)   [256:512) unused
//   A tile [32 k][72]  = 2304 floats : A0 @512,  A1 @2816
//   B tile [32 k][264] = 8448 floats : B0 @5120, B1 @13568
#define SMF_A(b)  (512 + (b) * 2304)
#define SMF_B(b)  (5120 + (b) * 8448)
#define SM_SZ     (22016 * 4)

// ---- k_convt SMEM float-index layout (512 threads, M=128 = 2 rows):
//   [0:256) s1   [256:512) t1
//   A buf b @ 512 + b*4608 (row r at +r*2304, each [32 k][72])
//   B buf b @ 9728 + b*8448 ([32 k][264])
#define CT_SMF_A(b) (512 + (b) * 4608)
#define CT_SMF_B(b) (9728 + (b) * 8448)
#define CT_SM_SZ    (26624 * 4)

// ---------------- weight prep -----------------------------------------------
__global__ void prep_wd(const float* __restrict__ w) {  // w_dcn [o][c][3][3]
    int idx = blockIdx.x * blockDim.x + threadIdx.x;
    if (idx >= 9 * 65536) return;
    int tap = idx >> 16, c = (idx >> 8) & 255, o = idx & 255;
    g_wdT[idx] = __uint_as_float(to_tf32(w[((o << 8) + c) * 9 + tap]));
}

__global__ void prep_wct(const float* __restrict__ w) {  // w_ct [i][o][4][4]
    int idx = blockIdx.x * blockDim.x + threadIdx.x;
    if (idx >= 16 * 65536) return;
    int q = idx >> 16, c = (idx >> 8) & 255, o = idx & 255;
    int par = q >> 2, tp = q & 3;
    int py = par >> 1, px = par & 1, ty = tp >> 1, tx = tp & 1;
    int a = py ? (ty ? 0 : 2) : (ty ? 1 : 3);
    int b = px ? (tx ? 0 : 2) : (tx ? 1 : 3);
    g_wctT[idx] = __uint_as_float(to_tf32(w[(((c << 8) + o) << 4) + (a << 2) + b]));
}

__global__ void prep_wo(const float* __restrict__ w) {  // w_off [27][c][3][3]; also zeroes g_red
    int idx = blockIdx.x * blockDim.x + threadIdx.x;
    if (idx < 1024) g_red[idx] = 0.0;
    if (idx >= 9 * 256 * 32) return;
    int tap = idx >> 13, c = (idx >> 5) & 255, o = idx & 31;
    g_woT[idx] = (o < 27) ? w[((o << 8) + c) * 9 + tap] : 0.f;
}

// ---------------- offset conv: 256->27(pad 32), 3x3 SAME (fp32, exact) ------
__global__ void __launch_bounds__(256, 2) k_off(const float* __restrict__ x,
                                                const float* __restrict__ boff) {
    extern __shared__ float vsm[];             // [256 c][64 p]
    const int t = threadIdx.x, y = blockIdx.x, n = blockIdx.y;
    const int o  = t & 31;
    const int p0 = (t >> 5) * 8;
    const int p  = t & 63;
    const int cg = t >> 6;

    ull acc[4];
    float bo = (o < 27) ? boff[o] : 0.f;
    ull bb = pk2(bo, bo);
    acc[0] = bb; acc[1] = bb; acc[2] = bb; acc[3] = bb;

    const float* xn = x + ((size_t)n << 20);

    for (int tap = 0; tap < 9; tap++) {
        const int ki = tap / 3, kj = tap - 3 * ki;
        const int yy = y + ki - 1;
        const int xx = p + kj - 1;
        const bool valid = (yy >= 0) && (yy < 64) && (xx >= 0) && (xx < 64);
        const float* src = xn + yy * 64 + xx;
        #pragma unroll 4
        for (int i = 0; i < 64; i++) {
            const int c = cg + (i << 2);
            vsm[(c << 6) + p] = valid ? src[(size_t)c << 12] : 0.f;
        }
        __syncthreads();
        const float* wb = g_woT + ((tap << 8) << 5);
        #pragma unroll 2
        for (int c = 0; c < 256; c++) {
            float w = wb[(c << 5) + o];
            ull wd = pk2(w, w);
            const ulonglong2* vp = (const ulonglong2*)(vsm + (c << 6) + p0);
            ulonglong2 va = vp[0], vb = vp[1];
            ffma2(acc[0], wd, va.x);
            ffma2(acc[1], wd, va.y);
            ffma2(acc[2], wd, vb.x);
            ffma2(acc[3], wd, vb.y);
        }
        __syncthreads();
    }

    if (o < 27) {
        float f0,f1,f2,f3,f4,f5,f6,f7;
        upk2(acc[0], f0, f1); upk2(acc[1], f2, f3);
        upk2(acc[2], f4, f5); upk2(acc[3], f6, f7);
        float* op = g_om + (((size_t)(n * 27 + o) * 64 + y) << 6) + p0;
        *(float4*)op       = make_float4(f0, f1, f2, f3);
        *(float4*)(op + 4) = make_float4(f4, f5, f6, f7);
    }
}

// ---------------- shared mma tile compute (round-7 proven form) --------------
__device__ __forceinline__ void mma_tile(float d[4][4][4], const float* Af,
                                         const float* Bf, int ng, int g, int tid) {
    const uint32_t* Au = (const uint32_t*)Af;
    const uint32_t* Bu = (const uint32_t*)Bf;
    #pragma unroll
    for (int ks = 0; ks < 4; ks++) {
        const int k0 = (ks << 3) + tid;
        uint32_t a[4][4];
        #pragma unroll
        for (int mt = 0; mt < 4; mt++) {
            const int r0 = (mt << 4) + g;
            a[mt][0] = Au[k0 * 72 + r0];
            a[mt][1] = Au[k0 * 72 + r0 + 8];
            a[mt][2] = Au[(k0 + 4) * 72 + r0];
            a[mt][3] = Au[(k0 + 4) * 72 + r0 + 8];
        }
        #pragma unroll
        for (int nt = 0; nt < 4; nt++) {
            const int nb = (ng << 5) + (nt << 3) + g;
            uint32_t b0 = Bu[k0 * 264 + nb];
            uint32_t b1 = Bu[(k0 + 4) * 264 + nb];
            #pragma unroll
            for (int mt = 0; mt < 4; mt++)
                MMA_TF32(d[mt][nt], a[mt], b0, b1);
        }
    }
}

// B stage via cp.async (256-thread version): 8x16B per thread = 2048 float4.
__device__ __forceinline__ void stage_B_async(uint32_t sbase, int bufB,
                                              const float* img, int t) {
    #pragma unroll
    for (int i = 0; i < 8; i++) {
        int idx = t + (i << 8);
        int cl = idx >> 6, o4 = (idx & 63) << 2;
        cp_async16(sbase + (uint32_t)(bufB + cl * 264 + o4) * 4, img + (idx << 2));
    }
    CP_COMMIT();
}

// B stage via cp.async (512-thread version): 4x16B per thread = 2048 float4 exact.
__device__ __forceinline__ void stage_B_async512(uint32_t sbase, int bufB,
                                                 const float* img, int t) {
    #pragma unroll
    for (int i = 0; i < 4; i++) {
        int idx = t + (i << 9);
        int cl = idx >> 6, o4 = (idx & 63) << 2;
        cp_async16(sbase + (uint32_t)(bufB + cl * 264 + o4) * 4, img + (idx << 2));
    }
    CP_COMMIT();
}

// ---------------- DCNv2 via tf32 mma.sync (round-11 verbatim) ----------------
__global__ void __launch_bounds__(256, 2) k_dcn_mma(const float* __restrict__ x,
                                                    const float* __restrict__ bdcn) {
    extern __shared__ __align__(16) float smf[];
    const uint32_t sbase = smem_u32(smf);
    const int t = threadIdx.x, y = blockIdx.x, n = blockIdx.y;
    const int wid = t >> 5, lane = t & 31;
    const int g = lane >> 2, tid = lane & 3;
    const int p = t & 63, cq = t >> 6;

    smf[t] = bdcn[t];                           // bias in [0:256)

    float d[4][4][4];
    #pragma unroll
    for (int i = 0; i < 4; i++)
        #pragma unroll
        for (int j = 0; j < 4; j++)
            #pragma unroll
            for (int k = 0; k < 4; k++) d[i][j][k] = 0.f;

    const float* xn = x + ((size_t)n << 20);
    float wr0 = 0.f, wr1 = 0.f, wc0 = 0.f, wc1 = 0.f;
    int abase = 0;
    float va[8];

    #define DCN_PARAMS(tap_) do { \
        const int ki = (tap_) / 3, kj = (tap_) - 3 * ki; \
        const float offy = g_om[(((n * 27 + 2 * (tap_))     * 64 + y) << 6) + p]; \
        const float offx = g_om[(((n * 27 + 2 * (tap_) + 1) * 64 + y) << 6) + p]; \
        const float mm   = g_om[(((n * 27 + 18 + (tap_))    * 64 + y) << 6) + p]; \
        const float mask = 1.f / (1.f + __expf(-mm)); \
        const float ys = (float)(y + ki - 1) + offy; \
        const float xs = (float)(p + kj - 1) + offx; \
        const float fy0 = floorf(ys), fx0 = floorf(xs); \
        const float dy = ys - fy0, dx = xs - fx0; \
        const int iy0 = (int)fy0, ix0 = (int)fx0; \
        wr0 = (iy0 >= 0 && iy0 <= 62) ? (1.f - dy) : ((iy0 == -1) ? dy : 0.f); \
        wr1 = (iy0 >= 0 && iy0 <= 62) ? dy : ((iy0 == 63) ? (1.f - dy) : 0.f); \
        wc0 = (ix0 >= 0 && ix0 <= 62) ? (1.f - dx) : ((ix0 == -1) ? dx : 0.f); \
        wc1 = (ix0 >= 0 && ix0 <= 62) ? dx : ((ix0 == 63) ? (1.f - dx) : 0.f); \
        wr0 *= mask; wr1 *= mask; \
        const int rb = min(max(iy0, 0), 62), cb = min(max(ix0, 0), 62); \
        abase = rb * 64 + cb; \
    } while (0)

    #define DCN_GATHER(kc_) do { \
        _Pragma("unroll") \
        for (int j = 0; j < 8; j++) { \
            const int cl = (cq << 3) + j; \
            const float* xc = xn + ((size_t)(((kc_) << 5) + cl) << 12); \
            va[j] = wr0 * (wc0 * xc[abase]      + wc1 * xc[abase + 1]) \
                  + wr1 * (wc0 * xc[abase + 64] + wc1 * xc[abase + 65]); \
        } \
    } while (0)

    #define STS_A(bufA_) do { \
        float* dstA = smf + (bufA_); \
        _Pragma("unroll") \
        for (int j = 0; j < 8; j++) { \
            const int cl = (cq << 3) + j; \
            dstA[cl * 72 + p] = __uint_as_float(to_tf32(va[j])); \
        } \
    } while (0)

    // prologue: stage chunk 0 into buffer 0
    DCN_PARAMS(0);
    stage_B_async(sbase, SMF_B(0), g_wdT, t);
    DCN_GATHER(0);
    STS_A(SMF_A(0));
    CP_WAIT0();
    __syncthreads();

    for (int it = 0; it < 72; it++) {
        const int buf = it & 1;
        if (it < 71) {
            const int s = it + 1;
            const int stap = s >> 3, skc = s & 7;
            if (skc == 0) DCN_PARAMS(stap);
            stage_B_async(sbase, SMF_B(buf ^ 1),
                          g_wdT + (((size_t)(stap << 8) + (skc << 5)) << 8), t);
            DCN_GATHER(skc);
        }
        mma_tile(d, smf + SMF_A(buf), smf + SMF_B(buf), wid, g, tid);
        if (it < 71) STS_A(SMF_A(buf ^ 1));
        CP_WAIT0();
        __syncthreads();
    }

    // epilogue: +bias, store to g_out1[n][o][y][x]; fused BN1 stats
    float rs[4][2], rq[4][2];
    #pragma unroll
    for (int nt = 0; nt < 4; nt++) { rs[nt][0] = rs[nt][1] = rq[nt][0] = rq[nt][1] = 0.f; }

    float* ob = g_out1 + ((size_t)n << 20) + (y << 6);
    #pragma unroll
    for (int mt = 0; mt < 4; mt++) {
        const int x0 = (mt << 4) + g;
        #pragma unroll
        for (int nt = 0; nt < 4; nt++) {
            const int o0 = (wid << 5) + (nt << 3) + (tid << 1);
            const float b0v = smf[o0], b1v = smf[o0 + 1];
            float w0 = d[mt][nt][0] + b0v, w1 = d[mt][nt][1] + b1v;
            float w2 = d[mt][nt][2] + b0v, w3 = d[mt][nt][3] + b1v;
            ob[((size_t)o0 << 12) + x0]           = w0;
            ob[((size_t)(o0 + 1) << 12) + x0]     = w1;
            ob[((size_t)o0 << 12) + x0 + 8]       = w2;
            ob[((size_t)(o0 + 1) << 12) + x0 + 8] = w3;
            rs[nt][0] += w0 + w2;  rq[nt][0] += w0 * w0 + w2 * w2;
            rs[nt][1] += w1 + w3;  rq[nt][1] += w1 * w1 + w3 * w3;
        }
    }
    #pragma unroll
    for (int nt = 0; nt < 4; nt++)
        #pragma unroll
        for (int c2 = 0; c2 < 2; c2++) {
            float s = rs[nt][c2], q = rq[nt][c2];
            #pragma unroll
            for (int off = 4; off < 32; off <<= 1) {
                s += __shfl_down_sync(0xffffffffu, s, off);
                q += __shfl_down_sync(0xffffffffu, q, off);
            }
            if (lane < 4) {
                const int ch = (wid << 5) + (nt << 3) + (tid << 1) + c2;
                atomicAdd(&g_red[ch], (double)s);
                atomicAdd(&g_red[256 + ch], (double)q);
            }
        }
}

// ---------------- convT via tf32 mma.sync: 512 thr, M=128 (2 rows) ----------
__global__ void __launch_bounds__(512, 1) k_convt_mma() {
    extern __shared__ __align__(16) float smf[];
    const uint32_t sbase = smem_u32(smf);
    const int t = threadIdx.x, by = blockIdx.x, n = blockIdx.y, par = blockIdx.z;
    const int py = par >> 1, pxs = par & 1;
    const int wid = t >> 5, lane = t & 31;
    const int g = lane >> 2, tid = lane & 3;
    const int ng = wid & 7, mg = wid >> 3;
    const int y0 = by << 1;
    // gather decomposition: 512 thr x 8 vals = 32c x 128px
    const int p2 = t & 127;                 // pixel in 2-row tile
    const int grow = p2 >> 6, gx = p2 & 63; // gather row, x
    const int cq2 = t >> 7;                 // 0..3 channel quarter

    if (t < 256) { smf[t] = g_s1[t]; smf[256 + t] = g_t1[t]; }

    float d[4][4][4];
    #pragma unroll
    for (int i = 0; i < 4; i++)
        #pragma unroll
        for (int j = 0; j < 4; j++)
            #pragma unroll
            for (int k = 0; k < 4; k++) d[i][j][k] = 0.f;

    const float* srcn = g_out1 + ((size_t)n << 20);
    int soff = 0; bool valid = false;
    float va[8];

    #define CT_PARAMS(tp_) do { \
        const int t_y = (tp_) >> 1, t_x = (tp_) & 1; \
        const int yy = y0 + grow + t_y - 1 + py; \
        const int xx = gx + t_x - 1 + pxs; \
        valid = (yy >= 0) && (yy < 64) && (xx >= 0) && (xx < 64); \
        soff = valid ? (yy * 64 + xx) : 0; \
    } while (0)

    #define CT_GATHER(kc_) do { \
        _Pragma("unroll") \
        for (int j = 0; j < 8; j++) { \
            const int cl = (cq2 << 3) + j; \
            const int c = ((kc_) << 5) + cl; \
            float v = 0.f; \
            if (valid) { \
                float r = srcn[((size_t)c << 12) + soff]; \
                v = fmaxf(smf[c] * r + smf[256 + c], 0.f); \
            } \
            va[j] = v; \
        } \
    } while (0)

    #define CT_STS_A(bufA_) do { \
        float* dstA = smf + (bufA_) + grow * 2304; \
        _Pragma("unroll") \
        for (int j = 0; j < 8; j++) { \
            const int cl = (cq2 << 3) + j; \
            dstA[cl * 72 + gx] = __uint_as_float(to_tf32(va[j])); \
        } \
    } while (0)

    // s1/t1 must be visible before CT_GATHER reads them
    __syncthreads();

    CT_PARAMS(0);
    stage_B_async512(sbase, CT_SMF_B(0), g_wctT + (((size_t)(par * 4) << 8) << 8), t);
    CT_GATHER(0);
    CT_STS_A(CT_SMF_A(0));
    CP_WAIT0();
    __syncthreads();

    for (int it = 0; it < 32; it++) {
        const int buf = it & 1;
        if (it < 31) {
            const int s = it + 1;
            const int stp = s >> 3, skc = s & 7;
            if (skc == 0) CT_PARAMS(stp);
            stage_B_async512(sbase, CT_SMF_B(buf ^ 1),
                             g_wctT + (((size_t)((par * 4 + stp) << 8) + (skc << 5)) << 8), t);
            CT_GATHER(skc);
        }
        mma_tile(d, smf + CT_SMF_A(buf) + mg * 2304, smf + CT_SMF_B(buf), ng, g, tid);
        if (it < 31) CT_STS_A(CT_SMF_A(buf ^ 1));
        CP_WAIT0();
        __syncthreads();
    }

    // epilogue: store raw; fused BN2 stats
    float rs[4][2], rq[4][2];
    #pragma unroll
    for (int nt = 0; nt < 4; nt++) { rs[nt][0] = rs[nt][1] = rq[nt][0] = rq[nt][1] = 0.f; }

    float* ob = g_raw + (((size_t)par * 8 + n) << 20) + ((y0 + mg) << 6);
    #pragma unroll
    for (int mt = 0; mt < 4; mt++) {
        const int x0 = (mt << 4) + g;
        #pragma unroll
        for (int nt = 0; nt < 4; nt++) {
            const int o0 = (ng << 5) + (nt << 3) + (tid << 1);
            float w0 = d[mt][nt][0], w1 = d[mt][nt][1];
            float w2 = d[mt][nt][2], w3 = d[mt][nt][3];
            ob[((size_t)o0 << 12) + x0]           = w0;
            ob[((size_t)(o0 + 1) << 12) + x0]     = w1;
            ob[((size_t)o0 << 12) + x0 + 8]       = w2;
            ob[((size_t)(o0 + 1) << 12) + x0 + 8] = w3;
            rs[nt][0] += w0 + w2;  rq[nt][0] += w0 * w0 + w2 * w2;
            rs[nt][1] += w1 + w3;  rq[nt][1] += w1 * w1 + w3 * w3;
        }
    }
    #pragma unroll
    for (int nt = 0; nt < 4; nt++)
        #pragma unroll
        for (int c2 = 0; c2 < 2; c2++) {
            float s = rs[nt][c2], q = rq[nt][c2];
            #pragma unroll
            for (int off = 4; off < 32; off <<= 1) {
                s += __shfl_down_sync(0xffffffffu, s, off);
                q += __shfl_down_sync(0xffffffffu, q, off);
            }
            if (lane < 4) {
                const int ch = (ng << 5) + (nt << 3) + (tid << 1) + c2;
                atomicAdd(&g_red[512 + ch], (double)s);
                atomicAdd(&g_red[768 + ch], (double)q);
            }
        }
}

// ---------------- BN stats --------------------------------------------------
__global__ void k_stats1(const float* __restrict__ g, const float* __restrict__ b) {
    int t = threadIdx.x;
    double sum = g_red[t], sq = g_red[256 + t];
    double m = sum / 32768.0;
    float var = (float)(sq / 32768.0 - m * m);
    var = fmaxf(var, 0.f);
    float s = g[t] * rsqrtf(var + EPS);
    g_s1[t] = s;
    g_t1[t] = b[t] - (float)m * s;
}

__global__ void k_stats2(const float* __restrict__ g, const float* __restrict__ b) {
    int t = threadIdx.x;
    double sum = g_red[512 + t], sq = g_red[768 + t];
    double m = sum / 131072.0;
    float var = (float)(sq / 131072.0 - m * m);
    var = fmaxf(var, 0.f);
    float s = g[t] * rsqrtf(var + EPS);
    g_s2[t] = s;
    g_t2[t] = b[t] - (float)m * s;
}

// ---------------- finalize: BN2 + ReLU, de-interleave parities --------------
__global__ void k_final(float* __restrict__ out) {
    int idx = blockIdx.x * 256 + threadIdx.x;
    int tx = idx & 63;
    int oy = (idx >> 6) & 127;
    int o  = (idx >> 13) & 255;
    int n  = idx >> 21;
    int py = oy & 1, ty = oy >> 1;
    size_t b0 = ((((size_t)(2 * py + 0) * 8 + n) * 256 + o) << 12) + (ty << 6) + tx;
    size_t b1 = ((((size_t)(2 * py + 1) * 8 + n) * 256 + o) << 12) + (ty << 6) + tx;
    float r0 = g_raw[b0], r1 = g_raw[b1];
    float s = g_s2[o], tt = g_t2[o];
    float2 w2;
    w2.x = fmaxf(s * r0 + tt, 0.f);
    w2.y = fmaxf(s * r1 + tt, 0.f);
    *(float2*)(out + ((((size_t)n * 256 + o) * 128 + oy) << 7) + 2 * tx) = w2;
}

// ---------------- launch ----------------------------------------------------
extern "C" void kernel_launch(void* const* d_in, const int* in_sizes, int n_in,
                              void* d_out, int out_size) {
    const float* x      = (const float*)d_in[0];
    const float* w_off  = (const float*)d_in[1];
    const float* b_off  = (const float*)d_in[2];
    const float* w_dcn  = (const float*)d_in[3];
    const float* b_dcn  = (const float*)d_in[4];
    const float* gamma1 = (const float*)d_in[5];
    const float* beta1  = (const float*)d_in[6];
    const float* w_ct   = (const float*)d_in[7];
    const float* gamma2 = (const float*)d_in[8];
    const float* beta2  = (const float*)d_in[9];
    float* out = (float*)d_out;

    cudaFuncSetAttribute(k_off,       cudaFuncAttributeMaxDynamicSharedMemorySize, 65536);
    cudaFuncSetAttribute(k_dcn_mma,   cudaFuncAttributeMaxDynamicSharedMemorySize, SM_SZ);
    cudaFuncSetAttribute(k_convt_mma, cudaFuncAttributeMaxDynamicSharedMemorySize, CT_SM_SZ);

    prep_wd<<<(9 * 65536 + 255) / 256, 256>>>(w_dcn);
    prep_wct<<<(16 * 65536 + 255) / 256, 256>>>(w_ct);
    prep_wo<<<(9 * 256 * 32 + 255) / 256, 256>>>(w_off);

    k_off<<<dim3(64, 8), 256, 65536>>>(x, b_off);
    k_dcn_mma<<<dim3(64, 8), 256, SM_SZ>>>(x, b_dcn);

    k_stats1<<<1, 256>>>(gamma1, beta1);

    k_convt_mma<<<dim3(32, 8, 4), 512, CT_SM_SZ>>>();

    k_stats2<<<1, 256>>>(gamma2, beta2);

    k_final<<<65536, 256>>>(out);
}